// round 1
// baseline (speedup 1.0000x reference)
#include <cuda_runtime.h>
#include <math.h>

// Problem constants
#define BB 4
#define TT 2048
#define CC 1024
#define HH 16
#define HD 64
#define MROWS (BB * TT)          // 8192
#define N_QKV (3 * CC)           // 3072

// Scratch (static device globals: allocation-free)
__device__ float g_q[BB * HH * TT * HD];   // [b*H+h][T][hd]
__device__ float g_k[BB * HH * TT * HD];
__device__ float g_v[BB * HH * TT * HD];
__device__ float g_att[BB * TT * CC];      // [B,T,C] pre-projection

// ---------------------------------------------------------------------------
// NT SGEMM: C[m,n] = sum_k A[m,k] * B[n,k].  128x128 tile, 8x8 micro, 256 thr.
// Two instances differing only in epilogue.
// ---------------------------------------------------------------------------

__global__ __launch_bounds__(256) void qkv_kernel(const float* __restrict__ X,
                                                  const float* __restrict__ W) {
    __shared__ float As[16][132];
    __shared__ float Bs[16][132];
    const int tid = threadIdx.x;
    const int m0 = blockIdx.y * 128;
    const int n0 = blockIdx.x * 128;
    const int tx = tid & 15;
    const int ty = tid >> 4;

    float acc[8][8];
#pragma unroll
    for (int i = 0; i < 8; i++)
#pragma unroll
        for (int j = 0; j < 8; j++) acc[i][j] = 0.f;

    for (int kk = 0; kk < CC; kk += 16) {
#pragma unroll
        for (int l = 0; l < 2; l++) {
            int e = tid + l * 256;          // 0..511
            int r = e >> 2;                 // 0..127
            int c4 = (e & 3) * 4;           // 0,4,8,12
            float4 va = *(const float4*)(X + (size_t)(m0 + r) * CC + kk + c4);
            As[c4 + 0][r] = va.x; As[c4 + 1][r] = va.y;
            As[c4 + 2][r] = va.z; As[c4 + 3][r] = va.w;
            float4 vb = *(const float4*)(W + (size_t)(n0 + r) * CC + kk + c4);
            Bs[c4 + 0][r] = vb.x; Bs[c4 + 1][r] = vb.y;
            Bs[c4 + 2][r] = vb.z; Bs[c4 + 3][r] = vb.w;
        }
        __syncthreads();
#pragma unroll
        for (int k = 0; k < 16; k++) {
            float a[8], b[8];
            *(float4*)&a[0] = *(const float4*)&As[k][ty * 8];
            *(float4*)&a[4] = *(const float4*)&As[k][ty * 8 + 4];
            *(float4*)&b[0] = *(const float4*)&Bs[k][tx * 8];
            *(float4*)&b[4] = *(const float4*)&Bs[k][tx * 8 + 4];
#pragma unroll
            for (int i = 0; i < 8; i++)
#pragma unroll
                for (int j = 0; j < 8; j++) acc[i][j] += a[i] * b[j];
        }
        __syncthreads();
    }

    // Scatter epilogue: n -> (head h, part q/k/v, dim d); write [b*H+h][t][d]
#pragma unroll
    for (int i = 0; i < 8; i++) {
        int m = m0 + ty * 8 + i;
        int b = m >> 11;                    // /2048
        int t = m & 2047;
#pragma unroll
        for (int j = 0; j < 8; j++) {
            int n = n0 + tx * 8 + j;
            int h = n / 192;
            int rr = n - h * 192;
            int part = rr >> 6;
            int d = rr & 63;
            float* dst = (part == 0) ? g_q : (part == 1) ? g_k : g_v;
            dst[(((size_t)(b * HH + h)) * TT + t) * HD + d] = acc[i][j];
        }
    }
}

__global__ __launch_bounds__(256) void proj_kernel(const float* __restrict__ W,
                                                   const float* __restrict__ bias,
                                                   float* __restrict__ out) {
    __shared__ float As[16][132];
    __shared__ float Bs[16][132];
    const int tid = threadIdx.x;
    const int m0 = blockIdx.y * 128;
    const int n0 = blockIdx.x * 128;
    const int tx = tid & 15;
    const int ty = tid >> 4;

    float acc[8][8];
#pragma unroll
    for (int i = 0; i < 8; i++)
#pragma unroll
        for (int j = 0; j < 8; j++) acc[i][j] = 0.f;

    for (int kk = 0; kk < CC; kk += 16) {
#pragma unroll
        for (int l = 0; l < 2; l++) {
            int e = tid + l * 256;
            int r = e >> 2;
            int c4 = (e & 3) * 4;
            float4 va = *(const float4*)(g_att + (size_t)(m0 + r) * CC + kk + c4);
            As[c4 + 0][r] = va.x; As[c4 + 1][r] = va.y;
            As[c4 + 2][r] = va.z; As[c4 + 3][r] = va.w;
            float4 vb = *(const float4*)(W + (size_t)(n0 + r) * CC + kk + c4);
            Bs[c4 + 0][r] = vb.x; Bs[c4 + 1][r] = vb.y;
            Bs[c4 + 2][r] = vb.z; Bs[c4 + 3][r] = vb.w;
        }
        __syncthreads();
#pragma unroll
        for (int k = 0; k < 16; k++) {
            float a[8], b[8];
            *(float4*)&a[0] = *(const float4*)&As[k][ty * 8];
            *(float4*)&a[4] = *(const float4*)&As[k][ty * 8 + 4];
            *(float4*)&b[0] = *(const float4*)&Bs[k][tx * 8];
            *(float4*)&b[4] = *(const float4*)&Bs[k][tx * 8 + 4];
#pragma unroll
            for (int i = 0; i < 8; i++)
#pragma unroll
                for (int j = 0; j < 8; j++) acc[i][j] += a[i] * b[j];
        }
        __syncthreads();
    }

#pragma unroll
    for (int i = 0; i < 8; i++) {
        int m = m0 + ty * 8 + i;
#pragma unroll
        for (int j = 0; j < 8; j++) {
            int n = n0 + tx * 8 + j;
            out[(size_t)m * CC + n] = acc[i][j] + bias[n];
        }
    }
}

// ---------------------------------------------------------------------------
// Flash attention, fp32. BM=128 q-rows, BN=64 k-rows, hd=64. 128 threads.
// Micro-tile 8x8 (ty=tid>>3 -> 8 rows, tx=tid&7 -> 8 cols/dims).
// Dynamic smem: Qst[64][132] (d-major), Kst[64][68], Vs[64][68], Pst[64][132].
// ---------------------------------------------------------------------------

#define ATT_SMEM_FLOATS (64 * 132 + 64 * 68 + 64 * 68 + 64 * 132)
#define ATT_SMEM_BYTES (ATT_SMEM_FLOATS * 4)

__global__ __launch_bounds__(128) void attn_kernel() {
    extern __shared__ float sm[];
    float(*Qst)[132] = (float(*)[132])sm;                        // [d][qrow]
    float(*Kst)[68]  = (float(*)[68])(sm + 64 * 132);            // [d][kcol]
    float(*Vs)[68]   = (float(*)[68])(sm + 64 * 132 + 64 * 68);  // [krow][d]
    float(*Pst)[132] = (float(*)[132])(sm + 64 * 132 + 2 * 64 * 68); // [kcol][qrow]

    const int tid = threadIdx.x;
    const int bh = blockIdx.y;                // b*H + h
    const int q0 = blockIdx.x * 128;
    const float* Qb = g_q + (size_t)bh * TT * HD;
    const float* Kb = g_k + (size_t)bh * TT * HD;
    const float* Vb = g_v + (size_t)bh * TT * HD;
    const int tx = tid & 7;                   // col/dim group
    const int ty = tid >> 3;                  // row group 0..15

    // Load Q tile transposed: 128 rows x 64 d
#pragma unroll
    for (int l = 0; l < 16; l++) {
        int e = l * 128 + tid;                // 0..2047 float4 units
        int r = e >> 4;                       // 0..127
        int c4 = (e & 15) * 4;
        float4 v = *(const float4*)(Qb + (size_t)(q0 + r) * HD + c4);
        Qst[c4 + 0][r] = v.x; Qst[c4 + 1][r] = v.y;
        Qst[c4 + 2][r] = v.z; Qst[c4 + 3][r] = v.w;
    }

    float o[8][8];
#pragma unroll
    for (int i = 0; i < 8; i++)
#pragma unroll
        for (int j = 0; j < 8; j++) o[i][j] = 0.f;
    float mr[8], lr[8];
#pragma unroll
    for (int i = 0; i < 8; i++) { mr[i] = -1e30f; lr[i] = 0.f; }

    const int jmax = (q0 >> 6) + 2;           // k-tiles cover cols <= q0+127

    for (int j = 0; j < jmax; j++) {
        const int k0 = j * 64;
        __syncthreads();                      // prior tile fully consumed
#pragma unroll
        for (int l = 0; l < 8; l++) {
            int e = l * 128 + tid;            // 0..1023 float4 units
            int r = e >> 4;                   // 0..63
            int c4 = (e & 15) * 4;
            float4 kv = *(const float4*)(Kb + (size_t)(k0 + r) * HD + c4);
            Kst[c4 + 0][r] = kv.x; Kst[c4 + 1][r] = kv.y;
            Kst[c4 + 2][r] = kv.z; Kst[c4 + 3][r] = kv.w;
            float4 vv = *(const float4*)(Vb + (size_t)(k0 + r) * HD + c4);
            *(float4*)&Vs[r][c4] = vv;
        }
        __syncthreads();

        // S = Q K^T (scaled)
        float s[8][8];
#pragma unroll
        for (int i = 0; i < 8; i++)
#pragma unroll
            for (int jj = 0; jj < 8; jj++) s[i][jj] = 0.f;
#pragma unroll 8
        for (int d = 0; d < 64; d++) {
            float qv[8], kv[8];
            *(float4*)&qv[0] = *(const float4*)&Qst[d][ty * 8];
            *(float4*)&qv[4] = *(const float4*)&Qst[d][ty * 8 + 4];
            *(float4*)&kv[0] = *(const float4*)&Kst[d][tx * 8];
            *(float4*)&kv[4] = *(const float4*)&Kst[d][tx * 8 + 4];
#pragma unroll
            for (int i = 0; i < 8; i++)
#pragma unroll
                for (int jj = 0; jj < 8; jj++) s[i][jj] += qv[i] * kv[jj];
        }
#pragma unroll
        for (int i = 0; i < 8; i++)
#pragma unroll
            for (int jj = 0; jj < 8; jj++) s[i][jj] *= 0.125f;

        // Causal mask (only the <=2 diagonal-overlapping tiles)
        if (k0 + 63 > q0) {
#pragma unroll
            for (int i = 0; i < 8; i++) {
                int qg = q0 + ty * 8 + i;
#pragma unroll
                for (int jj = 0; jj < 8; jj++) {
                    int kg = k0 + tx * 8 + jj;
                    if (kg > qg) s[i][jj] = -1e30f;
                }
            }
        }

        // Online softmax per row (stats replicated across the 8 tx lanes)
#pragma unroll
        for (int i = 0; i < 8; i++) {
            float mx = s[i][0];
#pragma unroll
            for (int jj = 1; jj < 8; jj++) mx = fmaxf(mx, s[i][jj]);
            mx = fmaxf(mx, __shfl_xor_sync(0xffffffffu, mx, 1));
            mx = fmaxf(mx, __shfl_xor_sync(0xffffffffu, mx, 2));
            mx = fmaxf(mx, __shfl_xor_sync(0xffffffffu, mx, 4));
            float mnew = fmaxf(mr[i], mx);
            float alpha = __expf(mr[i] - mnew);
            float sum = 0.f;
#pragma unroll
            for (int jj = 0; jj < 8; jj++) {
                float p = __expf(s[i][jj] - mnew);
                s[i][jj] = p;
                sum += p;
            }
            sum += __shfl_xor_sync(0xffffffffu, sum, 1);
            sum += __shfl_xor_sync(0xffffffffu, sum, 2);
            sum += __shfl_xor_sync(0xffffffffu, sum, 4);
            lr[i] = lr[i] * alpha + sum;
            mr[i] = mnew;
#pragma unroll
            for (int jj = 0; jj < 8; jj++) o[i][jj] *= alpha;
#pragma unroll
            for (int jj = 0; jj < 8; jj++)
                Pst[tx * 8 + jj][ty * 8 + i] = s[i][jj];
        }
        __syncthreads();                      // Pst visible across warps

        // O += P @ V
#pragma unroll 8
        for (int k = 0; k < 64; k++) {
            float pv[8], vv[8];
            *(float4*)&pv[0] = *(const float4*)&Pst[k][ty * 8];
            *(float4*)&pv[4] = *(const float4*)&Pst[k][ty * 8 + 4];
            *(float4*)&vv[0] = *(const float4*)&Vs[k][tx * 8];
            *(float4*)&vv[4] = *(const float4*)&Vs[k][tx * 8 + 4];
#pragma unroll
            for (int i = 0; i < 8; i++)
#pragma unroll
                for (int jj = 0; jj < 8; jj++) o[i][jj] += pv[i] * vv[jj];
        }
    }

    // Epilogue: normalize and write to g_att [B,T,C] with C = h*64 + d
    const int b = bh >> 4;
    const int h = bh & 15;
#pragma unroll
    for (int i = 0; i < 8; i++) {
        int t = q0 + ty * 8 + i;
        float inv = 1.f / lr[i];
#pragma unroll
        for (int jj = 0; jj < 8; jj++) {
            g_att[((size_t)(b * TT + t)) * CC + h * HD + tx * 8 + jj] = o[i][jj] * inv;
        }
    }
}

// ---------------------------------------------------------------------------

extern "C" void kernel_launch(void* const* d_in, const int* in_sizes, int n_in,
                              void* d_out, int out_size) {
    const float* x      = (const float*)d_in[0];
    const float* w_qkv  = (const float*)d_in[1];
    const float* w_proj = (const float*)d_in[2];
    const float* b_proj = (const float*)d_in[3];
    float* out = (float*)d_out;

    cudaFuncSetAttribute(attn_kernel, cudaFuncAttributeMaxDynamicSharedMemorySize,
                         ATT_SMEM_BYTES);

    qkv_kernel<<<dim3(N_QKV / 128, MROWS / 128), 256>>>(x, w_qkv);
    attn_kernel<<<dim3(TT / 128, BB * HH), 128, ATT_SMEM_BYTES>>>();
    proj_kernel<<<dim3(CC / 128, MROWS / 128), 256>>>(w_proj, b_proj, out);
}